// round 15
// baseline (speedup 1.0000x reference)
#include <cuda_runtime.h>
#include <math.h>
#include <stdint.h>

#define Bn 2
#define Nn 512
#define Dn 64
#define EPSf 1e-8f

#define EST_OFF  ((size_t)0)
#define OUT_OFF  ((size_t)131072)
#define QIJ_OFF  ((size_t)262144)
#define Z_OFF    ((size_t)1310720)
#define LH_OFF   ((size_t)68419584)

// ---- device scratch ----
__device__ __align__(16) float g_t[Nn];
__device__ __align__(16) float g_efr[Nn*Dn];
__device__ __align__(16) float g_efi[Nn*Dn];
__device__ __align__(16) float g_Uq[Bn*Nn*128];      // [row][e]
__device__ __align__(16) float g_UkT[Bn*128*Nn];     // [b][e][j]
__device__ __align__(16) float g_Uv[Bn*Nn*128];      // [row][e]
__device__ __align__(16) float g_V [Bn*Nn*128];
__device__ __align__(16) float g_eP[4][Bn*Nn*128];   // split-k partials
__device__ __align__(16) float g_s [Bn*Nn*Nn];       // 2MB scratch
__device__ float g_nq[Bn*Nn];
__device__ float g_nk[Bn*Nn];

// scores: 32i x 64j causal tiles, 72 per b
__device__ const int SC_IT2[72] = {
    0,1,2,2,3,3,4,4,4,5,5,5,6,6,6,6,7,7,7,7,
    8,8,8,8,8,9,9,9,9,9,10,10,10,10,10,10,11,11,11,11,11,11,
    12,12,12,12,12,12,12,13,13,13,13,13,13,13,
    14,14,14,14,14,14,14,14,15,15,15,15,15,15,15,15};
__device__ const int SC_JT2[72] = {
    0,0,0,1,0,1,0,1,2,0,1,2,0,1,2,3,0,1,2,3,
    0,1,2,3,4,0,1,2,3,4,0,1,2,3,4,5,0,1,2,3,4,5,
    0,1,2,3,4,5,6,0,1,2,3,4,5,6,
    0,1,2,3,4,5,6,7,0,1,2,3,4,5,6,7};
// av: 32i tiles x 128j chunks, 40 per b
__device__ const int AV_IT2[40] = {
    0,1,2,3, 4,4,5,5,6,6,7,7, 8,8,8,9,9,9,10,10,10,11,11,11,
    12,12,12,12,13,13,13,13,14,14,14,14,15,15,15,15};
__device__ const int AV_CH2[40] = {
    0,0,0,0, 0,1,0,1,0,1,0,1, 0,1,2,0,1,2,0,1,2,0,1,2,
    0,1,2,3,0,1,2,3,0,1,2,3,0,1,2,3};

// ============================================================
// K0: t, e^{i phi} tables, lambda_h output
// ============================================================
__global__ void k_setup(const float* __restrict__ tm,
                        const float* __restrict__ lv,
                        float* __restrict__ out_lh)
{
    int idx = blockIdx.x * blockDim.x + threadIdx.x;
    int i = idx >> 6;
    int d = idx & 63;
    float denom = tm[Nn - 1] - tm[0];
    float ti = tm[i] / denom;
    float lam = (d < 32) ? lv[d] : -lv[d - 32];
    float sph, cph;
    sincosf(ti * lam, &sph, &cph);
    g_efr[idx] = cph;
    g_efi[idx] = sph;
    if (d == 0) g_t[i] = ti;
    if (idx < 128) {
        float v;
        if (idx < 64) v = 0.f;
        else {
            int k = idx - 64;
            v = (k < 32) ? lv[k] : -lv[k - 32];
        }
        out_lh[idx] = v;
    }
}

// ============================================================
// K1: complex projections + twist. grid (256,3) ; 4 rows/block
// ============================================================
__global__ void __launch_bounds__(256) k_proj(
    const float* __restrict__ Zq, const float* __restrict__ Zk,
    const float* __restrict__ Zv,
    const float* __restrict__ Wq, const float* __restrict__ bq,
    const float* __restrict__ Wk, const float* __restrict__ bk,
    const float* __restrict__ Wv, const float* __restrict__ bv)
{
    int m   = blockIdx.y;
    int tid = threadIdx.x;
    int d   = tid & 63;
    int sub = tid >> 6;

    const float* Z  = (m == 0) ? Zq : (m == 1) ? Zk : Zv;
    const float* W  = (m == 0) ? Wq : (m == 1) ? Wk : Wv;
    const float* bb = (m == 0) ? bq : (m == 1) ? bk : bv;

    __shared__ float sW0[64 * 65];
    __shared__ float sW1[64 * 65];
    __shared__ float zbuf[4][2][64];
    __shared__ float part[8];

    {
        const float4* W04 = (const float4*)W;
        const float4* W14 = (const float4*)(W + 4096);
#pragma unroll
        for (int idx4 = tid; idx4 < 1024; idx4 += 256) {
            int r = idx4 >> 4, c = (idx4 & 15) * 4;
            float4 v0 = W04[idx4];
            float4 v1 = W14[idx4];
            float* p0 = sW0 + r * 65 + c;
            float* p1 = sW1 + r * 65 + c;
            p0[0] = v0.x; p0[1] = v0.y; p0[2] = v0.z; p0[3] = v0.w;
            p1[0] = v1.x; p1[1] = v1.y; p1[2] = v1.z; p1[3] = v1.w;
        }
    }
    float bR = bb[d], bI = bb[64 + d];

    int row = blockIdx.x * 4 + sub;
    int b = row >> 9, i = row & 511;

    zbuf[sub][0][d] = Z[((size_t)(b * 2 + 0) * Nn + i) * Dn + d];
    zbuf[sub][1][d] = Z[((size_t)(b * 2 + 1) * Nn + i) * Dn + d];
    __syncthreads();

    float yr = bR, yi = bI;
#pragma unroll 16
    for (int e = 0; e < 64; e++) {
        float w0 = sW0[d * 65 + e];
        float w1 = sW1[d * 65 + e];
        float a = zbuf[sub][0][e];
        float c = zbuf[sub][1][e];
        yr += a * w0 - c * w1;
        yi += a * w1 + c * w0;
    }

    float efr = g_efr[i * 64 + d];
    float efi = g_efi[i * 64 + d];
    float ur = efr * yr + efi * yi;
    float ui = efr * yi - efi * yr;

    if (m == 0)      { g_Uq[row * 128 + d] = ur; g_Uq[row * 128 + 64 + d] = ui; }
    else if (m == 1) { g_UkT[b * 65536 + d * 512 + i]        = ur;
                       g_UkT[b * 65536 + (64 + d) * 512 + i] = ui; }
    else             { g_Uv[row * 128 + d] = ur; g_Uv[row * 128 + 64 + d] = ui;
                       g_V [row * 128 + d] = yr; g_V [row * 128 + 64 + d] = yi; }

    if (m < 2) {
        float v = ur * ur + ui * ui;
#pragma unroll
        for (int off = 16; off > 0; off >>= 1)
            v += __shfl_down_sync(0xffffffffu, v, off);
        if ((tid & 31) == 0) part[tid >> 5] = v;
        __syncthreads();
        if (d == 0) {
            float tot = part[sub * 2] + part[sub * 2 + 1];
            if (m == 0) g_nq[row] = tot;
            else        g_nk[row] = tot;
        }
    }
}

// ============================================================
// K2a: scores GEMM. 32i x 64j tiles. grid 144.
// ============================================================
__global__ void __launch_bounds__(256) k_scores(
    const float* __restrict__ losq, const float* __restrict__ lgsq,
    const float* __restrict__ nfp,  const float* __restrict__ taup)
{
    extern __shared__ float sm[];
    float* sQT = sm;               // [128 e][36]
    float* sK  = sm + 128 * 36;    // [128 e][68]

    int bid = blockIdx.x;
    int b   = bid / 72;
    int t72 = bid % 72;
    int it  = SC_IT2[t72], jt = SC_JT2[t72];
    int i0  = it * 32, j0 = jt * 64;

    int tid = threadIdx.x;
    int tx  = tid & 31;
    int ty  = tid >> 5;

    {
        const float4* q4 = (const float4*)(g_Uq + (size_t)(b * 512 + i0) * 128);
        for (int idx4 = tid; idx4 < 32 * 32; idx4 += 256) {
            int r = idx4 >> 5;
            int e = (idx4 & 31) * 4;
            float4 v = q4[idx4];
            sQT[(e + 0) * 36 + r] = v.x;
            sQT[(e + 1) * 36 + r] = v.y;
            sQT[(e + 2) * 36 + r] = v.z;
            sQT[(e + 3) * 36 + r] = v.w;
        }
    }
    {
        const float* src = g_UkT + b * 65536 + j0;
        for (int idx4 = tid; idx4 < 128 * 16; idx4 += 256) {
            int e = idx4 >> 4, c = (idx4 & 15) * 4;
            float4 v = ((const float4*)(src + e * 512))[idx4 & 15];
            float* p = sK + e * 68 + c;
            p[0] = v.x; p[1] = v.y; p[2] = v.z; p[3] = v.w;
        }
    }
    __syncthreads();

    float c[4][2];
#pragma unroll
    for (int a = 0; a < 4; a++) { c[a][0] = 0.f; c[a][1] = 0.f; }

#pragma unroll 8
    for (int e = 0; e < 128; e++) {
        float4 aq = *(const float4*)(sQT + e * 36 + ty * 4);
        float2 kk = *(const float2*)(sK  + e * 68 + tx * 2);
        c[0][0] += aq.x * kk.x; c[0][1] += aq.x * kk.y;
        c[1][0] += aq.y * kk.x; c[1][1] += aq.y * kk.y;
        c[2][0] += aq.z * kk.x; c[2][1] += aq.z * kk.y;
        c[3][0] += aq.w * kk.x; c[3][1] += aq.w * kk.y;
    }

    float lo   = losq[0] * losq[0];
    float lg   = lgsq[0] * lgsq[0] + EPSf;
    float nf2  = nfp[0] * nfp[0] + EPSf;
    float tau2 = taup[0] * taup[0];

    int jb = j0 + tx * 2;
    float tj0 = g_t[jb],  tj1 = g_t[jb + 1];
    float nk0 = g_nk[b * 512 + jb], nk1 = g_nk[b * 512 + jb + 1];

#pragma unroll
    for (int a = 0; a < 4; a++) {
        int i = i0 + ty * 4 + a;
        float ti = g_t[i];
        float nq = g_nq[b * 512 + i];
        float r0 = (jb     <= i) ? (-tau2 * logf(nf2*(lo*fabsf(ti-tj0)+lg) + nq + nk0 - 2.f*c[a][0])) : -INFINITY;
        float r1 = (jb + 1 <= i) ? (-tau2 * logf(nf2*(lo*fabsf(ti-tj1)+lg) + nq + nk1 - 2.f*c[a][1])) : -INFINITY;
        *(float2*)(g_s + ((size_t)(b * 512 + i) * 512 + jb)) = make_float2(r0, r1);
    }
}

// ============================================================
// K2b: softmax rows + write A real plane
// ============================================================
__global__ void __launch_bounds__(256) k_softmax(float* __restrict__ out)
{
    int row = blockIdx.x;
    int b = row >> 9, i = row & 511;
    int tid = threadIdx.x;

    __shared__ float red[256];
    float* srow = g_s + (size_t)row * 512;

    float v0 = (tid     <= i) ? srow[tid]       : -INFINITY;
    float v1 = (tid+256 <= i) ? srow[tid + 256] : -INFINITY;

    red[tid] = fmaxf(v0, v1);
    __syncthreads();
    for (int st = 128; st > 0; st >>= 1) {
        if (tid < st) red[tid] = fmaxf(red[tid], red[tid + st]);
        __syncthreads();
    }
    float mx = red[0];
    __syncthreads();

    float e0 = (tid     <= i) ? expf(v0 - mx) : 0.f;
    float e1 = (tid+256 <= i) ? expf(v1 - mx) : 0.f;
    red[tid] = e0 + e1;
    __syncthreads();
    for (int st = 128; st > 0; st >>= 1) {
        if (tid < st) red[tid] += red[tid + st];
        __syncthreads();
    }
    float inv = 1.f / red[0];

    float a0 = e0 * inv;
    float a1 = e1 * inv;
    srow[tid]       = a0;
    srow[tid + 256] = a1;
    size_t qoffr = QIJ_OFF + ((size_t)(b * 2 + 0) * 512 + i) * 512;
    out[qoffr + tid]       = a0;
    out[qoffr + tid + 256] = a1;
}

// ============================================================
// K2c: AV split-k GEMM. grid 80
// ============================================================
__global__ void __launch_bounds__(256) k_av()
{
    extern __shared__ float sm[];
    float* sAT = sm;               // [128 j][36]
    float* sV  = sm + 128 * 36;    // [128 j][128 e]

    int bid = blockIdx.x;
    int b   = bid / 40;
    int t40 = bid % 40;
    int it  = AV_IT2[t40];
    int ch  = AV_CH2[t40];
    int i0  = it * 32;
    int jc  = ch * 128;

    int tid = threadIdx.x;
    int tx  = tid & 31;
    int ty  = tid >> 5;

    for (int idx4 = tid; idx4 < 32 * 32; idx4 += 256) {
        int r = idx4 >> 5;
        int j = (idx4 & 31) * 4;
        float4 v = *(const float4*)(g_s + ((size_t)(b * 512 + i0 + r) * 512 + jc + j));
        sAT[(j + 0) * 36 + r] = v.x;
        sAT[(j + 1) * 36 + r] = v.y;
        sAT[(j + 2) * 36 + r] = v.z;
        sAT[(j + 3) * 36 + r] = v.w;
    }
    {
        const float4* src = (const float4*)(g_Uv + (size_t)(b * 512 + jc) * 128);
        for (int idx4 = tid; idx4 < 128 * 32; idx4 += 256)
            ((float4*)sV)[idx4] = src[idx4];
    }
    __syncthreads();

    float c[4][4];
#pragma unroll
    for (int a = 0; a < 4; a++)
#pragma unroll
        for (int q = 0; q < 4; q++) c[a][q] = 0.f;

#pragma unroll 8
    for (int j = 0; j < 128; j++) {
        float4 aa = *(const float4*)(sAT + j * 36 + ty * 4);
        float4 vv = *(const float4*)(sV + j * 128 + tx * 4);
        c[0][0] += aa.x * vv.x; c[0][1] += aa.x * vv.y; c[0][2] += aa.x * vv.z; c[0][3] += aa.x * vv.w;
        c[1][0] += aa.y * vv.x; c[1][1] += aa.y * vv.y; c[1][2] += aa.y * vv.z; c[1][3] += aa.y * vv.w;
        c[2][0] += aa.z * vv.x; c[2][1] += aa.z * vv.y; c[2][2] += aa.z * vv.z; c[2][3] += aa.z * vv.w;
        c[3][0] += aa.w * vv.x; c[3][1] += aa.w * vv.y; c[3][2] += aa.w * vv.z; c[3][3] += aa.w * vv.w;
    }

    float* dstP = g_eP[ch];
#pragma unroll
    for (int a = 0; a < 4; a++) {
        float* dst = dstP + (size_t)(b * 512 + i0 + ty * 4 + a) * 128 + tx * 4;
        *(float4*)dst = make_float4(c[a][0], c[a][1], c[a][2], c[a][3]);
    }
}

// ============================================================
// K3: epilogue with inline split-k reduce. grid 256
// ============================================================
__global__ void __launch_bounds__(256) k_epi(
    const float* __restrict__ Wp, const float* __restrict__ bp,
    const float* __restrict__ etap, float* __restrict__ out)
{
    int tid = threadIdx.x;
    int d   = tid & 63;
    int sub = tid >> 6;

    __shared__ float sW0[64 * 65];
    __shared__ float sW1[64 * 65];
    __shared__ float pbuf[4][2][64];

    {
        const float4* W04 = (const float4*)Wp;
        const float4* W14 = (const float4*)(Wp + 4096);
#pragma unroll
        for (int idx4 = tid; idx4 < 1024; idx4 += 256) {
            int r = idx4 >> 4, c = (idx4 & 15) * 4;
            float4 v0 = W04[idx4];
            float4 v1 = W14[idx4];
            float* p0 = sW0 + r * 65 + c;
            float* p1 = sW1 + r * 65 + c;
            p0[0] = v0.x; p0[1] = v0.y; p0[2] = v0.z; p0[3] = v0.w;
            p1[0] = v1.x; p1[1] = v1.y; p1[2] = v1.z; p1[3] = v1.w;
        }
    }
    float bR = bp[d], bI = bp[64 + d];
    float eta = 1.f / (1.f + expf(-etap[d]));
    float g   = 1.f / (1.f + expf(-eta));

    int row = blockIdx.x * 4 + sub;
    int b = row >> 9, i = row & 511;
    int nch = (i >> 7) + 1;

    float er = g_eP[0][row * 128 + d];
    float ei = g_eP[0][row * 128 + 64 + d];
    if (nch > 1) { er += g_eP[1][row * 128 + d]; ei += g_eP[1][row * 128 + 64 + d]; }
    if (nch > 2) { er += g_eP[2][row * 128 + d]; ei += g_eP[2][row * 128 + 64 + d]; }
    if (nch > 3) { er += g_eP[3][row * 128 + d]; ei += g_eP[3][row * 128 + 64 + d]; }

    float efr = g_efr[i * 64 + d];
    float efi = g_efi[i * 64 + d];
    float estr = efr * er - efi * ei;
    float esti = efr * ei + efi * er;

    float elr = (1.f - eta) * g_V[row * 128 + d]      + g * estr;
    float eli = (1.f - eta) * g_V[row * 128 + 64 + d] + g * esti;

    out[EST_OFF + ((size_t)(b * 2 + 0) * 512 + i) * 64 + d] = elr;
    out[EST_OFF + ((size_t)(b * 2 + 1) * 512 + i) * 64 + d] = eli;

    pbuf[sub][0][d] = efr * elr - efi * eli;
    pbuf[sub][1][d] = efr * eli + efi * elr;
    __syncthreads();

    float yr = bR, yi = bI;
#pragma unroll 16
    for (int e = 0; e < 64; e++) {
        float w0 = sW0[d * 65 + e];
        float w1 = sW1[d * 65 + e];
        float a = pbuf[sub][0][e];
        float c = pbuf[sub][1][e];
        yr += a * w0 - c * w1;
        yi += a * w1 + c * w0;
    }
    out[OUT_OFF + ((size_t)(b * 2 + 0) * 512 + i) * 64 + d] = yr;
    out[OUT_OFF + ((size_t)(b * 2 + 1) * 512 + i) * 64 + d] = yi;
}

// ============================================================
// K4: Z_ij_hat_all + qimag. grid 130 ; block 512.
// blocks [0,128): 8 i-rows each, 16 warps (<=1 block/SM; bigger issue share)
// blocks [128,130): zero Q_ij imag planes (one 1MB plane each)
// ============================================================
__global__ void __launch_bounds__(512) k_zij(float* __restrict__ out)
{
    int blk = blockIdx.x;
    int tid = threadIdx.x;

    if (blk >= 128) {
        int plane = blk - 128;                // 0 -> b0 imag, 1 -> b1 imag
        float4* p = (float4*)(out + QIJ_OFF + (size_t)(plane * 2 + 1) * 262144);
        float4 z = {0.f, 0.f, 0.f, 0.f};
#pragma unroll 8
        for (int k = 0; k < 128; k++)
            __stcs(&p[tid + k * 512], z);
        return;
    }

    int b   = blk >> 6;
    int i0  = (blk & 63) * 8;
    int d4  = tid & 15;
    int d   = d4 << 2;
    int jb  = tid >> 4;                       // 0..31

    float er[8][4], ei[8][4];
#pragma unroll
    for (int il = 0; il < 8; il++)
#pragma unroll
        for (int q = 0; q < 4; q++) {
            er[il][q] = g_efr[(i0 + il) * 64 + d + q];
            ei[il][q] = g_efi[(i0 + il) * 64 + d + q];
        }

    const float4* uv = (const float4*)(g_Uv + (size_t)b * 65536);
    float4* zrb = (float4*)(out + Z_OFF + ((size_t)(b * 2 + 0) * 512 + i0) * 32768);
    float4* zib = (float4*)(out + Z_OFF + ((size_t)(b * 2 + 1) * 512 + i0) * 32768);

#pragma unroll 2
    for (int j = jb; j < 512; j += 32) {
        float4 vr = __ldg(&uv[j * 32 + d4]);
        float4 vi = __ldg(&uv[j * 32 + 16 + d4]);
        int o = j * 16 + d4;
#pragma unroll
        for (int il = 0; il < 8; il++) {
            float4 a, c;
            a.x = er[il][0]*vr.x - ei[il][0]*vi.x;  c.x = er[il][0]*vi.x + ei[il][0]*vr.x;
            a.y = er[il][1]*vr.y - ei[il][1]*vi.y;  c.y = er[il][1]*vi.y + ei[il][1]*vr.y;
            a.z = er[il][2]*vr.z - ei[il][2]*vi.z;  c.z = er[il][2]*vi.z + ei[il][2]*vr.z;
            a.w = er[il][3]*vr.w - ei[il][3]*vi.w;  c.w = er[il][3]*vi.w + ei[il][3]*vr.w;
            __stcs(&zrb[il * 8192 + o], a);
            __stcs(&zib[il * 8192 + o], c);
        }
    }
}

// ============================================================
extern "C" void kernel_launch(void* const* d_in, const int* in_sizes, int n_in,
                              void* d_out, int out_size)
{
    const float* Zq   = (const float*)d_in[0];
    const float* Zk   = (const float*)d_in[1];
    const float* Zv   = (const float*)d_in[2];
    const float* tm   = (const float*)d_in[3];
    const float* Wq   = (const float*)d_in[4];
    const float* bq   = (const float*)d_in[5];
    const float* Wk   = (const float*)d_in[6];
    const float* bk   = (const float*)d_in[7];
    const float* Wv   = (const float*)d_in[8];
    const float* bv   = (const float*)d_in[9];
    const float* Wp   = (const float*)d_in[10];
    const float* bp   = (const float*)d_in[11];
    const float* lv   = (const float*)d_in[12];
    const float* losq = (const float*)d_in[13];
    const float* lgsq = (const float*)d_in[14];
    const float* nf   = (const float*)d_in[15];
    const float* tau  = (const float*)d_in[16];
    const float* etap = (const float*)d_in[17];
    float* out = (float*)d_out;

    static cudaStream_t s_c = nullptr;      // HIGH-priority chain stream
    static cudaEvent_t ev_fork = nullptr, ev_join = nullptr;
    static const int sc_smem = (128 * 36 + 128 * 68) * 4;    // ~53KB
    static const int av_smem = (128 * 36 + 128 * 128) * 4;   // ~84KB
    if (s_c == nullptr) {
        int lo, hi;
        cudaDeviceGetStreamPriorityRange(&lo, &hi);
        cudaStreamCreateWithPriority(&s_c, cudaStreamNonBlocking, hi);
        cudaEventCreateWithFlags(&ev_fork, cudaEventDisableTiming);
        cudaEventCreateWithFlags(&ev_join, cudaEventDisableTiming);
        cudaFuncSetAttribute(k_scores, cudaFuncAttributeMaxDynamicSharedMemorySize, sc_smem);
        cudaFuncSetAttribute(k_av,     cudaFuncAttributeMaxDynamicSharedMemorySize, av_smem);
    }

    // R11 prologue exactly: setup then proj, serial on stream 0
    k_setup<<<64, 512>>>(tm, lv, out + LH_OFF);
    k_proj<<<dim3(256, 3), 256>>>(Zq, Zk, Zv, Wq, bq, Wk, bk, Wv, bv);

    // fork: chain (high prio, enqueued first) co-resides with zij
    cudaEventRecord(ev_fork, 0);
    cudaStreamWaitEvent(s_c, ev_fork, 0);
    k_scores<<<144, 256, sc_smem, s_c>>>(losq, lgsq, nf, tau);
    k_softmax<<<Bn * Nn, 256, 0, s_c>>>(out);
    k_av<<<80, 256, av_smem, s_c>>>();
    k_epi<<<256, 256, 0, s_c>>>(Wp, bp, etap, out);
    cudaEventRecord(ev_join, s_c);

    k_zij<<<130, 512>>>(out);

    cudaStreamWaitEvent(0, ev_join, 0);
}

// round 16
// speedup vs baseline: 1.1892x; 1.1892x over previous
#include <cuda_runtime.h>
#include <math.h>
#include <stdint.h>

#define Bn 2
#define Nn 512
#define Dn 64
#define EPSf 1e-8f

#define EST_OFF  ((size_t)0)
#define OUT_OFF  ((size_t)131072)
#define QIJ_OFF  ((size_t)262144)
#define Z_OFF    ((size_t)1310720)
#define LH_OFF   ((size_t)68419584)

// ---- device scratch ----
__device__ __align__(16) float g_t[Nn];
__device__ __align__(16) float g_efr[Nn*Dn];
__device__ __align__(16) float g_efi[Nn*Dn];
__device__ __align__(16) float g_Uq[Bn*Nn*128];      // [row][e]
__device__ __align__(16) float g_UkT[Bn*128*Nn];     // [b][e][j]
__device__ __align__(16) float g_Uv[Bn*Nn*128];      // [row][e]
__device__ __align__(16) float g_V [Bn*Nn*128];
__device__ __align__(16) float g_eP[4][Bn*Nn*128];   // split-k partials
__device__ __align__(16) float g_s [Bn*Nn*Nn];       // 2MB scratch
__device__ float g_nq[Bn*Nn];
__device__ float g_nk[Bn*Nn];

// scores: 32i x 64j causal tiles, 72 per b
__device__ const int SC_IT2[72] = {
    0,1,2,2,3,3,4,4,4,5,5,5,6,6,6,6,7,7,7,7,
    8,8,8,8,8,9,9,9,9,9,10,10,10,10,10,10,11,11,11,11,11,11,
    12,12,12,12,12,12,12,13,13,13,13,13,13,13,
    14,14,14,14,14,14,14,14,15,15,15,15,15,15,15,15};
__device__ const int SC_JT2[72] = {
    0,0,0,1,0,1,0,1,2,0,1,2,0,1,2,3,0,1,2,3,
    0,1,2,3,4,0,1,2,3,4,0,1,2,3,4,5,0,1,2,3,4,5,
    0,1,2,3,4,5,6,0,1,2,3,4,5,6,
    0,1,2,3,4,5,6,7,0,1,2,3,4,5,6,7};
// av: 32i tiles x 128j chunks, 40 per b
__device__ const int AV_IT2[40] = {
    0,1,2,3, 4,4,5,5,6,6,7,7, 8,8,8,9,9,9,10,10,10,11,11,11,
    12,12,12,12,13,13,13,13,14,14,14,14,15,15,15,15};
__device__ const int AV_CH2[40] = {
    0,0,0,0, 0,1,0,1,0,1,0,1, 0,1,2,0,1,2,0,1,2,0,1,2,
    0,1,2,3,0,1,2,3,0,1,2,3,0,1,2,3};

// ============================================================
// K0: t, e^{i phi} tables, lambda_h output
// ============================================================
__global__ void k_setup(const float* __restrict__ tm,
                        const float* __restrict__ lv,
                        float* __restrict__ out_lh)
{
    int idx = blockIdx.x * blockDim.x + threadIdx.x;
    int i = idx >> 6;
    int d = idx & 63;
    float denom = tm[Nn - 1] - tm[0];
    float ti = tm[i] / denom;
    float lam = (d < 32) ? lv[d] : -lv[d - 32];
    float sph, cph;
    sincosf(ti * lam, &sph, &cph);
    g_efr[idx] = cph;
    g_efi[idx] = sph;
    if (d == 0) g_t[i] = ti;
    if (idx < 128) {
        float v;
        if (idx < 64) v = 0.f;
        else {
            int k = idx - 64;
            v = (k < 32) ? lv[k] : -lv[k - 32];
        }
        out_lh[idx] = v;
    }
}

// ============================================================
// K1: complex projections + twist. grid (256,3) ; 4 rows/block
// ============================================================
__global__ void __launch_bounds__(256) k_proj(
    const float* __restrict__ Zq, const float* __restrict__ Zk,
    const float* __restrict__ Zv,
    const float* __restrict__ Wq, const float* __restrict__ bq,
    const float* __restrict__ Wk, const float* __restrict__ bk,
    const float* __restrict__ Wv, const float* __restrict__ bv)
{
    int m   = blockIdx.y;
    int tid = threadIdx.x;
    int d   = tid & 63;
    int sub = tid >> 6;

    const float* Z  = (m == 0) ? Zq : (m == 1) ? Zk : Zv;
    const float* W  = (m == 0) ? Wq : (m == 1) ? Wk : Wv;
    const float* bb = (m == 0) ? bq : (m == 1) ? bk : bv;

    __shared__ float sW0[64 * 65];
    __shared__ float sW1[64 * 65];
    __shared__ float zbuf[4][2][64];
    __shared__ float part[8];

    {
        const float4* W04 = (const float4*)W;
        const float4* W14 = (const float4*)(W + 4096);
#pragma unroll
        for (int idx4 = tid; idx4 < 1024; idx4 += 256) {
            int r = idx4 >> 4, c = (idx4 & 15) * 4;
            float4 v0 = W04[idx4];
            float4 v1 = W14[idx4];
            float* p0 = sW0 + r * 65 + c;
            float* p1 = sW1 + r * 65 + c;
            p0[0] = v0.x; p0[1] = v0.y; p0[2] = v0.z; p0[3] = v0.w;
            p1[0] = v1.x; p1[1] = v1.y; p1[2] = v1.z; p1[3] = v1.w;
        }
    }
    float bR = bb[d], bI = bb[64 + d];

    int row = blockIdx.x * 4 + sub;
    int b = row >> 9, i = row & 511;

    zbuf[sub][0][d] = Z[((size_t)(b * 2 + 0) * Nn + i) * Dn + d];
    zbuf[sub][1][d] = Z[((size_t)(b * 2 + 1) * Nn + i) * Dn + d];
    __syncthreads();

    float yr = bR, yi = bI;
#pragma unroll 16
    for (int e = 0; e < 64; e++) {
        float w0 = sW0[d * 65 + e];
        float w1 = sW1[d * 65 + e];
        float a = zbuf[sub][0][e];
        float c = zbuf[sub][1][e];
        yr += a * w0 - c * w1;
        yi += a * w1 + c * w0;
    }

    float efr = g_efr[i * 64 + d];
    float efi = g_efi[i * 64 + d];
    float ur = efr * yr + efi * yi;
    float ui = efr * yi - efi * yr;

    if (m == 0)      { g_Uq[row * 128 + d] = ur; g_Uq[row * 128 + 64 + d] = ui; }
    else if (m == 1) { g_UkT[b * 65536 + d * 512 + i]        = ur;
                       g_UkT[b * 65536 + (64 + d) * 512 + i] = ui; }
    else             { g_Uv[row * 128 + d] = ur; g_Uv[row * 128 + 64 + d] = ui;
                       g_V [row * 128 + d] = yr; g_V [row * 128 + 64 + d] = yi; }

    if (m < 2) {
        float v = ur * ur + ui * ui;
#pragma unroll
        for (int off = 16; off > 0; off >>= 1)
            v += __shfl_down_sync(0xffffffffu, v, off);
        if ((tid & 31) == 0) part[tid >> 5] = v;
        __syncthreads();
        if (d == 0) {
            float tot = part[sub * 2] + part[sub * 2 + 1];
            if (m == 0) g_nq[row] = tot;
            else        g_nk[row] = tot;
        }
    }
}

// ============================================================
// K2a: scores GEMM. 32i x 64j tiles. grid 144.
// ============================================================
__global__ void __launch_bounds__(256) k_scores(
    const float* __restrict__ losq, const float* __restrict__ lgsq,
    const float* __restrict__ nfp,  const float* __restrict__ taup)
{
    extern __shared__ float sm[];
    float* sQT = sm;               // [128 e][36]
    float* sK  = sm + 128 * 36;    // [128 e][68]

    int bid = blockIdx.x;
    int b   = bid / 72;
    int t72 = bid % 72;
    int it  = SC_IT2[t72], jt = SC_JT2[t72];
    int i0  = it * 32, j0 = jt * 64;

    int tid = threadIdx.x;
    int tx  = tid & 31;
    int ty  = tid >> 5;

    {
        const float4* q4 = (const float4*)(g_Uq + (size_t)(b * 512 + i0) * 128);
        for (int idx4 = tid; idx4 < 32 * 32; idx4 += 256) {
            int r = idx4 >> 5;
            int e = (idx4 & 31) * 4;
            float4 v = q4[idx4];
            sQT[(e + 0) * 36 + r] = v.x;
            sQT[(e + 1) * 36 + r] = v.y;
            sQT[(e + 2) * 36 + r] = v.z;
            sQT[(e + 3) * 36 + r] = v.w;
        }
    }
    {
        const float* src = g_UkT + b * 65536 + j0;
        for (int idx4 = tid; idx4 < 128 * 16; idx4 += 256) {
            int e = idx4 >> 4, c = (idx4 & 15) * 4;
            float4 v = ((const float4*)(src + e * 512))[idx4 & 15];
            float* p = sK + e * 68 + c;
            p[0] = v.x; p[1] = v.y; p[2] = v.z; p[3] = v.w;
        }
    }
    __syncthreads();

    float c[4][2];
#pragma unroll
    for (int a = 0; a < 4; a++) { c[a][0] = 0.f; c[a][1] = 0.f; }

#pragma unroll 8
    for (int e = 0; e < 128; e++) {
        float4 aq = *(const float4*)(sQT + e * 36 + ty * 4);
        float2 kk = *(const float2*)(sK  + e * 68 + tx * 2);
        c[0][0] += aq.x * kk.x; c[0][1] += aq.x * kk.y;
        c[1][0] += aq.y * kk.x; c[1][1] += aq.y * kk.y;
        c[2][0] += aq.z * kk.x; c[2][1] += aq.z * kk.y;
        c[3][0] += aq.w * kk.x; c[3][1] += aq.w * kk.y;
    }

    float lo   = losq[0] * losq[0];
    float lg   = lgsq[0] * lgsq[0] + EPSf;
    float nf2  = nfp[0] * nfp[0] + EPSf;
    float tau2 = taup[0] * taup[0];

    int jb = j0 + tx * 2;
    float tj0 = g_t[jb],  tj1 = g_t[jb + 1];
    float nk0 = g_nk[b * 512 + jb], nk1 = g_nk[b * 512 + jb + 1];

#pragma unroll
    for (int a = 0; a < 4; a++) {
        int i = i0 + ty * 4 + a;
        float ti = g_t[i];
        float nq = g_nq[b * 512 + i];
        float r0 = (jb     <= i) ? (-tau2 * logf(nf2*(lo*fabsf(ti-tj0)+lg) + nq + nk0 - 2.f*c[a][0])) : -INFINITY;
        float r1 = (jb + 1 <= i) ? (-tau2 * logf(nf2*(lo*fabsf(ti-tj1)+lg) + nq + nk1 - 2.f*c[a][1])) : -INFINITY;
        *(float2*)(g_s + ((size_t)(b * 512 + i) * 512 + jb)) = make_float2(r0, r1);
    }
}

// ============================================================
// K2b: softmax rows + write A real plane
// ============================================================
__global__ void __launch_bounds__(256) k_softmax(float* __restrict__ out)
{
    int row = blockIdx.x;
    int b = row >> 9, i = row & 511;
    int tid = threadIdx.x;

    __shared__ float red[256];
    float* srow = g_s + (size_t)row * 512;

    float v0 = (tid     <= i) ? srow[tid]       : -INFINITY;
    float v1 = (tid+256 <= i) ? srow[tid + 256] : -INFINITY;

    red[tid] = fmaxf(v0, v1);
    __syncthreads();
    for (int st = 128; st > 0; st >>= 1) {
        if (tid < st) red[tid] = fmaxf(red[tid], red[tid + st]);
        __syncthreads();
    }
    float mx = red[0];
    __syncthreads();

    float e0 = (tid     <= i) ? expf(v0 - mx) : 0.f;
    float e1 = (tid+256 <= i) ? expf(v1 - mx) : 0.f;
    red[tid] = e0 + e1;
    __syncthreads();
    for (int st = 128; st > 0; st >>= 1) {
        if (tid < st) red[tid] += red[tid + st];
        __syncthreads();
    }
    float inv = 1.f / red[0];

    float a0 = e0 * inv;
    float a1 = e1 * inv;
    srow[tid]       = a0;
    srow[tid + 256] = a1;
    size_t qoffr = QIJ_OFF + ((size_t)(b * 2 + 0) * 512 + i) * 512;
    out[qoffr + tid]       = a0;
    out[qoffr + tid + 256] = a1;
}

// ============================================================
// K2c: AV split-k GEMM. grid 80
// ============================================================
__global__ void __launch_bounds__(256) k_av()
{
    extern __shared__ float sm[];
    float* sAT = sm;               // [128 j][36]
    float* sV  = sm + 128 * 36;    // [128 j][128 e]

    int bid = blockIdx.x;
    int b   = bid / 40;
    int t40 = bid % 40;
    int it  = AV_IT2[t40];
    int ch  = AV_CH2[t40];
    int i0  = it * 32;
    int jc  = ch * 128;

    int tid = threadIdx.x;
    int tx  = tid & 31;
    int ty  = tid >> 5;

    for (int idx4 = tid; idx4 < 32 * 32; idx4 += 256) {
        int r = idx4 >> 5;
        int j = (idx4 & 31) * 4;
        float4 v = *(const float4*)(g_s + ((size_t)(b * 512 + i0 + r) * 512 + jc + j));
        sAT[(j + 0) * 36 + r] = v.x;
        sAT[(j + 1) * 36 + r] = v.y;
        sAT[(j + 2) * 36 + r] = v.z;
        sAT[(j + 3) * 36 + r] = v.w;
    }
    {
        const float4* src = (const float4*)(g_Uv + (size_t)(b * 512 + jc) * 128);
        for (int idx4 = tid; idx4 < 128 * 32; idx4 += 256)
            ((float4*)sV)[idx4] = src[idx4];
    }
    __syncthreads();

    float c[4][4];
#pragma unroll
    for (int a = 0; a < 4; a++)
#pragma unroll
        for (int q = 0; q < 4; q++) c[a][q] = 0.f;

#pragma unroll 8
    for (int j = 0; j < 128; j++) {
        float4 aa = *(const float4*)(sAT + j * 36 + ty * 4);
        float4 vv = *(const float4*)(sV + j * 128 + tx * 4);
        c[0][0] += aa.x * vv.x; c[0][1] += aa.x * vv.y; c[0][2] += aa.x * vv.z; c[0][3] += aa.x * vv.w;
        c[1][0] += aa.y * vv.x; c[1][1] += aa.y * vv.y; c[1][2] += aa.y * vv.z; c[1][3] += aa.y * vv.w;
        c[2][0] += aa.z * vv.x; c[2][1] += aa.z * vv.y; c[2][2] += aa.z * vv.z; c[2][3] += aa.z * vv.w;
        c[3][0] += aa.w * vv.x; c[3][1] += aa.w * vv.y; c[3][2] += aa.w * vv.z; c[3][3] += aa.w * vv.w;
    }

    float* dstP = g_eP[ch];
#pragma unroll
    for (int a = 0; a < 4; a++) {
        float* dst = dstP + (size_t)(b * 512 + i0 + ty * 4 + a) * 128 + tx * 4;
        *(float4*)dst = make_float4(c[a][0], c[a][1], c[a][2], c[a][3]);
    }
}

// ============================================================
// K3: epilogue with inline split-k reduce. grid 256
// ============================================================
__global__ void __launch_bounds__(256) k_epi(
    const float* __restrict__ Wp, const float* __restrict__ bp,
    const float* __restrict__ etap, float* __restrict__ out)
{
    int tid = threadIdx.x;
    int d   = tid & 63;
    int sub = tid >> 6;

    __shared__ float sW0[64 * 65];
    __shared__ float sW1[64 * 65];
    __shared__ float pbuf[4][2][64];

    {
        const float4* W04 = (const float4*)Wp;
        const float4* W14 = (const float4*)(Wp + 4096);
#pragma unroll
        for (int idx4 = tid; idx4 < 1024; idx4 += 256) {
            int r = idx4 >> 4, c = (idx4 & 15) * 4;
            float4 v0 = W04[idx4];
            float4 v1 = W14[idx4];
            float* p0 = sW0 + r * 65 + c;
            float* p1 = sW1 + r * 65 + c;
            p0[0] = v0.x; p0[1] = v0.y; p0[2] = v0.z; p0[3] = v0.w;
            p1[0] = v1.x; p1[1] = v1.y; p1[2] = v1.z; p1[3] = v1.w;
        }
    }
    float bR = bp[d], bI = bp[64 + d];
    float eta = 1.f / (1.f + expf(-etap[d]));
    float g   = 1.f / (1.f + expf(-eta));

    int row = blockIdx.x * 4 + sub;
    int b = row >> 9, i = row & 511;
    int nch = (i >> 7) + 1;

    float er = g_eP[0][row * 128 + d];
    float ei = g_eP[0][row * 128 + 64 + d];
    if (nch > 1) { er += g_eP[1][row * 128 + d]; ei += g_eP[1][row * 128 + 64 + d]; }
    if (nch > 2) { er += g_eP[2][row * 128 + d]; ei += g_eP[2][row * 128 + 64 + d]; }
    if (nch > 3) { er += g_eP[3][row * 128 + d]; ei += g_eP[3][row * 128 + 64 + d]; }

    float efr = g_efr[i * 64 + d];
    float efi = g_efi[i * 64 + d];
    float estr = efr * er - efi * ei;
    float esti = efr * ei + efi * er;

    float elr = (1.f - eta) * g_V[row * 128 + d]      + g * estr;
    float eli = (1.f - eta) * g_V[row * 128 + 64 + d] + g * esti;

    out[EST_OFF + ((size_t)(b * 2 + 0) * 512 + i) * 64 + d] = elr;
    out[EST_OFF + ((size_t)(b * 2 + 1) * 512 + i) * 64 + d] = eli;

    pbuf[sub][0][d] = efr * elr - efi * eli;
    pbuf[sub][1][d] = efr * eli + efi * elr;
    __syncthreads();

    float yr = bR, yi = bI;
#pragma unroll 16
    for (int e = 0; e < 64; e++) {
        float w0 = sW0[d * 65 + e];
        float w1 = sW1[d * 65 + e];
        float a = pbuf[sub][0][e];
        float c = pbuf[sub][1][e];
        yr += a * w0 - c * w1;
        yi += a * w1 + c * w0;
    }
    out[OUT_OFF + ((size_t)(b * 2 + 0) * 512 + i) * 64 + d] = yr;
    out[OUT_OFF + ((size_t)(b * 2 + 1) * 512 + i) * 64 + d] = yi;
}

// ============================================================
// K4: Z_ij_hat_all + qimag. grid 132 ; block 256.  (R11 proven config)
// blocks [0,128): 8 i-rows each (<=1 block/SM -> chain co-residency)
// blocks [128,132): zero Q_ij imag planes
// ============================================================
__global__ void __launch_bounds__(256) k_zij(float* __restrict__ out)
{
    int blk = blockIdx.x;
    int tid = threadIdx.x;

    if (blk >= 128) {
        int q = blk - 128;                    // 0..3
        int plane = q >> 1;
        int half  = q & 1;
        float4* p = (float4*)(out + QIJ_OFF + (size_t)(plane * 2 + 1) * 262144);
        float4 z = {0.f, 0.f, 0.f, 0.f};
        int base = half * 32768 + tid;
#pragma unroll 8
        for (int k = 0; k < 128; k++)
            __stcs(&p[base + k * 256], z);
        return;
    }

    int b   = blk >> 6;
    int i0  = (blk & 63) * 8;
    int d4  = tid & 15;
    int d   = d4 << 2;
    int jb  = tid >> 4;

    float er[8][4], ei[8][4];
#pragma unroll
    for (int il = 0; il < 8; il++)
#pragma unroll
        for (int q = 0; q < 4; q++) {
            er[il][q] = g_efr[(i0 + il) * 64 + d + q];
            ei[il][q] = g_efi[(i0 + il) * 64 + d + q];
        }

    const float4* uv = (const float4*)(g_Uv + (size_t)b * 65536);
    float4* zrb = (float4*)(out + Z_OFF + ((size_t)(b * 2 + 0) * 512 + i0) * 32768);
    float4* zib = (float4*)(out + Z_OFF + ((size_t)(b * 2 + 1) * 512 + i0) * 32768);

#pragma unroll 2
    for (int j = jb; j < 512; j += 16) {
        float4 vr = __ldg(&uv[j * 32 + d4]);
        float4 vi = __ldg(&uv[j * 32 + 16 + d4]);
        int o = j * 16 + d4;
#pragma unroll
        for (int il = 0; il < 8; il++) {
            float4 a, c;
            a.x = er[il][0]*vr.x - ei[il][0]*vi.x;  c.x = er[il][0]*vi.x + ei[il][0]*vr.x;
            a.y = er[il][1]*vr.y - ei[il][1]*vi.y;  c.y = er[il][1]*vi.y + ei[il][1]*vr.y;
            a.z = er[il][2]*vr.z - ei[il][2]*vi.z;  c.z = er[il][2]*vi.z + ei[il][2]*vr.z;
            a.w = er[il][3]*vr.w - ei[il][3]*vi.w;  c.w = er[il][3]*vi.w + ei[il][3]*vr.w;
            __stcs(&zrb[il * 8192 + o], a);
            __stcs(&zib[il * 8192 + o], c);
        }
    }
}

// ============================================================
extern "C" void kernel_launch(void* const* d_in, const int* in_sizes, int n_in,
                              void* d_out, int out_size)
{
    const float* Zq   = (const float*)d_in[0];
    const float* Zk   = (const float*)d_in[1];
    const float* Zv   = (const float*)d_in[2];
    const float* tm   = (const float*)d_in[3];
    const float* Wq   = (const float*)d_in[4];
    const float* bq   = (const float*)d_in[5];
    const float* Wk   = (const float*)d_in[6];
    const float* bk   = (const float*)d_in[7];
    const float* Wv   = (const float*)d_in[8];
    const float* bv   = (const float*)d_in[9];
    const float* Wp   = (const float*)d_in[10];
    const float* bp   = (const float*)d_in[11];
    const float* lv   = (const float*)d_in[12];
    const float* losq = (const float*)d_in[13];
    const float* lgsq = (const float*)d_in[14];
    const float* nf   = (const float*)d_in[15];
    const float* tau  = (const float*)d_in[16];
    const float* etap = (const float*)d_in[17];
    float* out = (float*)d_out;

    static cudaStream_t s_c = nullptr;      // HIGH-priority chain stream
    static cudaEvent_t ev_fork = nullptr, ev_join = nullptr;
    static const int sc_smem = (128 * 36 + 128 * 68) * 4;    // ~53KB
    static const int av_smem = (128 * 36 + 128 * 128) * 4;   // ~84KB
    if (s_c == nullptr) {
        int lo, hi;
        cudaDeviceGetStreamPriorityRange(&lo, &hi);   // hi = highest priority
        cudaStreamCreateWithPriority(&s_c, cudaStreamNonBlocking, hi);
        cudaEventCreateWithFlags(&ev_fork, cudaEventDisableTiming);
        cudaEventCreateWithFlags(&ev_join, cudaEventDisableTiming);
        cudaFuncSetAttribute(k_scores, cudaFuncAttributeMaxDynamicSharedMemorySize, sc_smem);
        cudaFuncSetAttribute(k_av,     cudaFuncAttributeMaxDynamicSharedMemorySize, av_smem);
    }

    k_setup<<<64, 512>>>(tm, lv, out + LH_OFF);
    k_proj<<<dim3(256, 3), 256>>>(Zq, Zk, Zv, Wq, bq, Wk, bk, Wv, bv);

    // fork: chain (high prio, latency-bound) co-resides with zij (1 blk/SM)
    cudaEventRecord(ev_fork, 0);
    cudaStreamWaitEvent(s_c, ev_fork, 0);
    k_scores<<<144, 256, sc_smem, s_c>>>(losq, lgsq, nf, tau);
    k_softmax<<<Bn * Nn, 256, 0, s_c>>>(out);
    k_av<<<80, 256, av_smem, s_c>>>();
    k_epi<<<256, 256, 0, s_c>>>(Wp, bp, etap, out);
    cudaEventRecord(ev_join, s_c);

    k_zij<<<132, 256>>>(out);

    cudaStreamWaitEvent(0, ev_join, 0);
}